// round 14
// baseline (speedup 1.0000x reference)
#include <cuda_runtime.h>
#include <cuda_bf16.h>

#define Bn 8
#define Sn 512
#define Kn 16
#define Rr 8            // output rows per block
#define SW (Sn + 4)     // padded shared row width (cols 0 and Sn+1 are zero)
#define TILES (Sn / Rr) // 64 blocks per batch
#define EMPTY_DIST 362.1f
#define FAR_COORD 1.0e18f

// Persistent scratch (no allocations allowed). Starts zeroed (.bss);
// the last block resets everything after use -> deterministic replays.
__device__ float    g_py[Bn][Kn];
__device__ float    g_px[Bn][Kn];
__device__ int      g_cnt[Bn];
__device__ int      g_scan_done[Bn];   // blocks of batch b that finished scanning
__device__ unsigned g_maxbits[Bn];
__device__ double   g_numer[Bn];
__device__ double   g_gradsum;
__device__ unsigned g_done;

// ---------------------------------------------------------------------------
// Single fused kernel: label scan + sobel + distance + reductions + finalize.
// grid (TILES, Bn), 512 threads, 4 blocks/SM, cooperative launch (whole grid
// co-resident). Phase order hides the per-batch spin behind the sobel:
//   scan -> arrive -> loads -> sync -> SOBEL -> spin -> DISTANCE -> reduce.
// ---------------------------------------------------------------------------
__global__ __launch_bounds__(512, 4) void fused_kernel(const float* __restrict__ pred,
                                                       const float* __restrict__ ori,
                                                       const float* __restrict__ ptl,
                                                       float* __restrict__ out) {
    __shared__ float s_img[Rr + 2][SW];     // cols 0 and Sn+1 are zero
    __shared__ float s_pred[Rr][Sn];        // own-column pred values (reg relief)
    __shared__ float sh_s[16], sh_g[16], sh_m[16];

    const int y0 = blockIdx.x * Rr;
    const int b  = blockIdx.y;
    const int x  = threadIdx.x;
    const int lane = x & 31;

    const float* __restrict__ pb = pred + b * (Sn * Sn);
    const float* __restrict__ ob = ori  + b * (Sn * Sn);

    // --- phase 0: scan this block's own row-slice of pt_label for points ---
    {
        const float4* ps = (const float4*)(ptl + b * (Sn * Sn) + y0 * Sn);
        #pragma unroll
        for (int i = 0; i < (Rr * Sn / 4) / 512; i++) {     // 2 float4 per thread
            int idx4 = x + i * 512;
            float4 v = ps[idx4];
            if (v.x != 0.f || v.y != 0.f || v.z != 0.f || v.w != 0.f) {
                float vv[4] = {v.x, v.y, v.z, v.w};
                #pragma unroll
                for (int j = 0; j < 4; j++) {
                    if (vv[j] != 0.f) {
                        int idx = y0 * Sn + idx4 * 4 + j;
                        int slot = atomicAdd(&g_cnt[b], 1);
                        if (slot < Kn) {
                            g_py[b][slot] = (float)(idx >> 9);
                            g_px[b][slot] = (float)(idx & (Sn - 1));
                        }
                    }
                }
            }
        }
    }
    __syncthreads();                 // all scan writes of this block done
    if (x == 0) {
        __threadfence();             // release g_px/g_py/g_cnt writes
        atomicAdd(&g_scan_done[b], 1);
    }

    if (x < 2) {
        int col = (x == 0) ? 0 : (Sn + 1);
        #pragma unroll
        for (int rr = 0; rr < Rr + 2; rr++) s_img[rr][col] = 0.f;
    }

    // --- phase 1: global loads + smem stores ---
    {   // top halo
        float v = 0.f;
        if (y0 > 0) {
            int o = (y0 - 1) * Sn + x;
            v = __ldg(pb + o) * __ldg(ob + o);
        }
        s_img[0][x + 1] = v;
    }
    #pragma unroll
    for (int rr = 1; rr <= Rr; rr++) {      // always in-range
        int o = (y0 + rr - 1) * Sn + x;
        float pval = __ldg(pb + o);
        s_pred[rr - 1][x] = pval;
        s_img[rr][x + 1] = pval * __ldg(ob + o);
    }
    {   // bottom halo
        float v = 0.f;
        if (y0 + Rr < Sn) {
            int o = (y0 + Rr) * Sn + x;
            v = __ldg(pb + o) * __ldg(ob + o);
        }
        s_img[Rr + 1][x + 1] = v;
    }
    __syncthreads();                 // s_img complete for sobel

    // --- phase 2: branch-free rolling-window sobel (no dependence on points) ---
    float gsum = 0.f;
    {
        const float xokf = (x >= 1 && x <= Sn - 2) ? 1.f : 0.f;

        float a0l = s_img[0][x], a0c = s_img[0][x + 1], a0r = s_img[0][x + 2];
        float a1l = s_img[1][x],                        a1r = s_img[1][x + 2];

        #pragma unroll
        for (int r = 0; r < Rr; r++) {
            const int y = y0 + r;
            float a2l = s_img[r + 2][x], a2c = s_img[r + 2][x + 1], a2r = s_img[r + 2][x + 2];

            float t = a0c - a2c;     // n01 - n21
            float u = a1r - a1l;     // n12 - n10
            float p = a0r - a2l;     // n02 - n20
            float q = a0l - a2r;     // n00 - n22
            float g0 = fmaf(2.f, u, p - q);
            float g1 = fmaf(2.f, t, p + q);
            float g2 = fmaf(2.f, q, t - u);
            float g3 = fmaf(2.f, p, t + u);
            float gm = fmaxf(fmaxf(fabsf(g0), fabsf(g1)), fmaxf(fabsf(g2), fabsf(g3)));
            float maskf = (y >= 1 && y <= Sn - 2) ? xokf : 0.f;  // y part block-uniform
            gsum = fmaf(maskf, gm, gsum);

            a0l = a1l; a0c = s_img[r + 1][x + 1]; a0r = a1r;
            a1l = a2l;                            a1r = a2r;
        }
    }

    // --- spin: by now all sibling scans are long finished (sobel hid them) ---
    if (x == 0) {
        while (atomicAdd(&g_scan_done[b], 0) < TILES) { __nanosleep(32); }
        __threadfence();             // acquire
    }
    __syncthreads();

    // point coords into registers (lane<16), broadcast via shfl
    int cload = 0;
    float pxv = FAR_COORD, pyv = FAR_COORD;
    if (lane == 0) cload = g_cnt[b];
    const int cnt = min(__shfl_sync(0xffffffffu, cload, 0), Kn);
    if (lane < Kn) {
        if (lane < cnt) { pxv = g_px[b][lane]; pyv = g_py[b][lane]; }
    }

    const float fx  = (float)x;
    const float fy0 = (float)y0;

    // --- phase 3a: exact per-warp point culling over the warp's 32xRr tile ---
    unsigned keep;
    {
        const float x0f = (float)(x & ~31);
        const float x1f = x0f + 31.0f;
        const float y1f = fy0 + (float)(Rr - 1);
        float lb = 3.0e38f, ubi = 3.0e38f;
        if (lane < Kn) {
            float dxl = x0f - pxv, dxr = pxv - x1f;
            float dxm = fmaxf(0.f, fmaxf(dxl, dxr));
            float dxM = fmaxf(fabsf(dxl), fabsf(x1f - pxv));
            float dyl = fy0 - pyv, dyr = pyv - y1f;
            float dym = fmaxf(0.f, fmaxf(dyl, dyr));
            float dyM = fmaxf(fabsf(dyl), fabsf(y1f - pyv));
            lb  = fmaf(dxm, dxm, dym * dym);
            ubi = fmaf(dxM, dxM, dyM * dyM);
        }
        float ub = ubi;
        #pragma unroll
        for (int o = 16; o > 0; o >>= 1)
            ub = fminf(ub, __shfl_xor_sync(0xffffffffu, ub, o));
        keep = __ballot_sync(0xffffffffu, lb <= ub);
    }

    // --- phase 3b: distance mins over surviving points (shfl-broadcast) ---
    float m[Rr];
    #pragma unroll
    for (int r = 0; r < Rr; r++) m[r] = 3.0e38f;

    unsigned mask = keep;
    while (mask) {
        int i = __ffs(mask) - 1;
        mask &= mask - 1;
        float px_i = __shfl_sync(0xffffffffu, pxv, i);
        float py_i = __shfl_sync(0xffffffffu, pyv, i);
        float dxv = fx - px_i;
        float dy0 = fy0 - py_i;
        float c = fmaf(dy0, dy0, dxv * dxv);
        float e = dy0 + dy0;
        #pragma unroll
        for (int r = 0; r < Rr; r++)
            m[r] = fminf(m[r], fmaf((float)r, e, c));       // d2(r) = m + r^2 later
    }

    float vsum = 0.f, vmax = 0.f;
    #pragma unroll
    for (int r = 0; r < Rr; r++) {
        float d2 = m[r] + (float)(r * r);
        float dist = (cnt > 0) ? sqrtf(d2) : EMPTY_DIST;
        float dd = fmaxf(dist - 1.0f, 0.f);
        vsum += s_pred[r][x] * dd;
        vmax = fmaxf(vmax, dd);
    }

    // --- block reduction: sum(vsum), sum(gsum), max(vmax) ---
    #pragma unroll
    for (int o = 16; o > 0; o >>= 1) {
        vsum += __shfl_down_sync(0xffffffffu, vsum, o);
        gsum += __shfl_down_sync(0xffffffffu, gsum, o);
        vmax = fmaxf(vmax, __shfl_down_sync(0xffffffffu, vmax, o));
    }
    const int wid = x >> 5;
    if (lane == 0) { sh_s[wid] = vsum; sh_g[wid] = gsum; sh_m[wid] = vmax; }
    __syncthreads();
    if (wid == 0) {
        vsum = (lane < 16) ? sh_s[lane] : 0.f;
        gsum = (lane < 16) ? sh_g[lane] : 0.f;
        vmax = (lane < 16) ? sh_m[lane] : 0.f;
        #pragma unroll
        for (int o = 8; o > 0; o >>= 1) {
            vsum += __shfl_down_sync(0xffffffffu, vsum, o);
            gsum += __shfl_down_sync(0xffffffffu, gsum, o);
            vmax = fmaxf(vmax, __shfl_down_sync(0xffffffffu, vmax, o));
        }
        if (lane == 0) {
            atomicAdd(&g_numer[b], (double)vsum);
            atomicAdd(&g_gradsum, (double)gsum);
            atomicMax(&g_maxbits[b], __float_as_uint(vmax));

            __threadfence();
            unsigned ticket = atomicAdd(&g_done, 1u);
            const unsigned total = TILES * Bn;
            if (ticket == total - 1u) {
                double acc = 0.0;
                #pragma unroll
                for (int bb = 0; bb < Bn; bb++) {
                    float mx = __uint_as_float(g_maxbits[bb]);
                    acc += g_numer[bb] / (double)mx;
                    g_numer[bb] = 0.0;
                    g_maxbits[bb] = 0u;
                    g_cnt[bb] = 0;
                    g_scan_done[bb] = 0;
                }
                const double denom = (double)Sn * (double)Sn * (double)Bn;
                out[0] = (float)(acc / denom);
                out[1] = (float)(g_gradsum / denom);
                g_gradsum = 0.0;
                g_done = 0u;
                __threadfence();
            }
        }
    }
}

extern "C" void kernel_launch(void* const* d_in, const int* in_sizes, int n_in,
                              void* d_out, int out_size) {
    const float* pred = (const float*)d_in[0];
    const float* ptl  = (const float*)d_in[1];
    const float* ori  = (const float*)d_in[2];
    float* out = (float*)d_out;

    void* args[] = { (void*)&pred, (void*)&ori, (void*)&ptl, (void*)&out };
    cudaLaunchCooperativeKernel((void*)fused_kernel,
                                dim3(TILES, Bn), dim3(512),
                                args, 0, (cudaStream_t)0);
}